// round 1
// baseline (speedup 1.0000x reference)
#include <cuda_runtime.h>
#include <cstdint>

#define B_  2
#define L_  512
#define T_  1024
#define E_  2560
#define H_  128
#define HW_ 20
#define F_  (2*E_)   // 5120

// Scratch (no cudaMalloc allowed)
__device__ float g_xe[B_*L_*E_];   // (1024, 2560)  10 MB
__device__ float g_t [B_*L_*F_];   // (1024, 5120)  20 MB

// ---------------------------------------------------------------------------
// tf32 helpers
// ---------------------------------------------------------------------------
__device__ __forceinline__ uint32_t f2tf32(float x) {
    uint32_t r;
    asm("cvt.rna.tf32.f32 %0, %1;" : "=r"(r) : "f"(x));
    return r;
}

__device__ __forceinline__ void mma_tf32(float (&d)[4], const uint32_t (&a)[4],
                                         const uint32_t (&b)[2]) {
    asm volatile(
        "mma.sync.aligned.m16n8k8.row.col.f32.tf32.tf32.f32 "
        "{%0,%1,%2,%3}, {%4,%5,%6,%7}, {%8,%9}, {%0,%1,%2,%3};"
        : "+f"(d[0]), "+f"(d[1]), "+f"(d[2]), "+f"(d[3])
        : "r"(a[0]), "r"(a[1]), "r"(a[2]), "r"(a[3]), "r"(b[0]), "r"(b[1]));
}

__device__ __forceinline__ void cp_async16(uint32_t smem, const void* g) {
    asm volatile("cp.async.cg.shared.global [%0], [%1], 16;" :: "r"(smem), "l"(g));
}

// ---------------------------------------------------------------------------
// GEMM: C[M,N] = A[M,K] (row) * W[N,K]^T (W row-major N x K)
// 128x128x16 tiles, 8 warps (2m x 4n), warp tile 64x32, tf32 mma m16n8k8,
// cp.async 2-stage pipeline.
// ---------------------------------------------------------------------------
#define BM 128
#define BN 128
#define BK 16
#define PAD 20   // row length in words (16 data + 4 pad) -> conflict-free frags

__global__ void __launch_bounds__(256) gemm_tf32_kernel(
    const float* __restrict__ A, const float* __restrict__ W,
    float* __restrict__ C, int M, int N, int K)
{
    __shared__ __align__(16) float As[2][BM][PAD];
    __shared__ __align__(16) float Ws[2][BN][PAD];

    const int tid  = threadIdx.x;
    const int warp = tid >> 5;
    const int lane = tid & 31;
    const int r = lane >> 2;      // 0..7
    const int c = lane & 3;       // 0..3
    const int wm = (warp >> 2) * 64;   // 0 / 64
    const int wn = (warp & 3) * 32;    // 0 / 32 / 64 / 96
    const int m0 = blockIdx.x * BM;
    const int n0 = blockIdx.y * BN;

    float acc[4][4][4];
    #pragma unroll
    for (int i = 0; i < 4; ++i)
        #pragma unroll
        for (int j = 0; j < 4; ++j)
            #pragma unroll
            for (int v = 0; v < 4; ++v) acc[i][j][v] = 0.0f;

    const int KT = K / BK;

    // stage loader: 1024 float4 copies (512 A + 512 W), 4 per thread
    #define LOAD_STAGE(st, kt)                                                 \
    {                                                                          \
        const int kbase = (kt) * BK;                                           \
        _Pragma("unroll")                                                      \
        for (int i = 0; i < 2; ++i) {                                          \
            int e = tid + i * 256;                                             \
            int m = e >> 2, v = e & 3;                                         \
            uint32_t da = (uint32_t)__cvta_generic_to_shared(&As[st][m][v*4]); \
            cp_async16(da, &A[(size_t)(m0 + m) * K + kbase + v * 4]);          \
            uint32_t dw = (uint32_t)__cvta_generic_to_shared(&Ws[st][m][v*4]); \
            cp_async16(dw, &W[(size_t)(n0 + m) * K + kbase + v * 4]);          \
        }                                                                      \
        asm volatile("cp.async.commit_group;");                                \
    }

    LOAD_STAGE(0, 0);

    for (int kt = 0; kt < KT; ++kt) {
        if (kt + 1 < KT) {
            LOAD_STAGE((kt + 1) & 1, kt + 1);
            asm volatile("cp.async.wait_group 1;");
        } else {
            asm volatile("cp.async.wait_group 0;");
        }
        __syncthreads();

        const int st = kt & 1;
        #pragma unroll
        for (int s = 0; s < 2; ++s) {
            uint32_t af[4][4], bf[4][2];
            #pragma unroll
            for (int i = 0; i < 4; ++i) {
                int m = wm + i * 16 + r;
                af[i][0] = f2tf32(As[st][m    ][s*8 + c    ]);
                af[i][1] = f2tf32(As[st][m + 8][s*8 + c    ]);
                af[i][2] = f2tf32(As[st][m    ][s*8 + c + 4]);
                af[i][3] = f2tf32(As[st][m + 8][s*8 + c + 4]);
            }
            #pragma unroll
            for (int j = 0; j < 4; ++j) {
                int n = wn + j * 8 + r;
                bf[j][0] = f2tf32(Ws[st][n][s*8 + c    ]);
                bf[j][1] = f2tf32(Ws[st][n][s*8 + c + 4]);
            }
            #pragma unroll
            for (int i = 0; i < 4; ++i)
                #pragma unroll
                for (int j = 0; j < 4; ++j)
                    mma_tf32(acc[i][j], af[i], bf[j]);
        }
        __syncthreads();
    }

    // epilogue
    #pragma unroll
    for (int i = 0; i < 4; ++i) {
        #pragma unroll
        for (int j = 0; j < 4; ++j) {
            int m = m0 + wm + i * 16 + r;
            int n = n0 + wn + j * 8 + 2 * c;
            C[(size_t)m * N + n]           = acc[i][j][0];
            C[(size_t)m * N + n + 1]       = acc[i][j][1];
            C[(size_t)(m + 8) * N + n]     = acc[i][j][2];
            C[(size_t)(m + 8) * N + n + 1] = acc[i][j][3];
        }
    }
    #undef LOAD_STAGE
}

// ---------------------------------------------------------------------------
// Fused epilogue:
//   t (1024, 5120) row (b,l): head h occupies cols [h*40, h*40+40);
//   q = cols [h*40, +20), k = cols [h*40+20, +20)
//   out[b,q,k,h] = mask[b,k] ? (q.k)*HW^-0.5 + bias[b,q,k,h] : 0
// Block: (b, 32 q, 32 k), loop over h in chunks of 8. 256 threads =
// (k_local, h_local) with h fastest -> 32B-sector coalesced bias/out.
// ---------------------------------------------------------------------------
__global__ void __launch_bounds__(256) attn_epilogue_kernel(
    const float* __restrict__ t, const int* __restrict__ mask,
    const float* __restrict__ bias, float* __restrict__ out)
{
    __shared__ __align__(16) float qs[32][8][20];
    __shared__ __align__(16) float ks[32][8][20];

    const int b  = blockIdx.z;
    const int q0 = blockIdx.y * 32;
    const int k0 = blockIdx.x * 32;
    const int tid = threadIdx.x;
    const int kl = tid >> 3;   // 0..31
    const int hl = tid & 7;    // 0..7
    const float scale = 0.22360679774997896f;   // 20^-0.5

    const int maskv = mask[b * L_ + k0 + kl];

    for (int hc = 0; hc < H_ / 8; ++hc) {
        __syncthreads();   // protect smem reuse from previous iteration
        #pragma unroll
        for (int i = 0; i < 20; ++i) {
            int e   = tid + i * 256;       // 0..5119
            int qq  = e / 160;
            int rem = e - qq * 160;
            int hh  = rem / 20;
            int cc  = rem - hh * 20;
            int col = (hc * 8 + hh) * 40 + cc;
            qs[qq][hh][cc] = t[(size_t)(b * L_ + q0 + qq) * F_ + col];
            ks[qq][hh][cc] = t[(size_t)(b * L_ + k0 + qq) * F_ + col + 20];
        }
        __syncthreads();

        const float4 kv0 = *(const float4*)&ks[kl][hl][0];
        const float4 kv1 = *(const float4*)&ks[kl][hl][4];
        const float4 kv2 = *(const float4*)&ks[kl][hl][8];
        const float4 kv3 = *(const float4*)&ks[kl][hl][12];
        const float4 kv4 = *(const float4*)&ks[kl][hl][16];

        #pragma unroll 4
        for (int q = 0; q < 32; ++q) {
            const float* qr = &qs[q][hl][0];
            const float4 a0 = *(const float4*)&qr[0];
            const float4 a1 = *(const float4*)&qr[4];
            const float4 a2 = *(const float4*)&qr[8];
            const float4 a3 = *(const float4*)&qr[12];
            const float4 a4 = *(const float4*)&qr[16];
            float acc = a0.x*kv0.x + a0.y*kv0.y + a0.z*kv0.z + a0.w*kv0.w
                      + a1.x*kv1.x + a1.y*kv1.y + a1.z*kv1.z + a1.w*kv1.w
                      + a2.x*kv2.x + a2.y*kv2.y + a2.z*kv2.z + a2.w*kv2.w
                      + a3.x*kv3.x + a3.y*kv3.y + a3.z*kv3.z + a3.w*kv3.w
                      + a4.x*kv4.x + a4.y*kv4.y + a4.z*kv4.z + a4.w*kv4.w;
            size_t oidx = ((size_t)(b * L_ + q0 + q) * L_ + (k0 + kl)) * H_
                        + hc * 8 + hl;
            out[oidx] = maskv ? fmaf(acc, scale, bias[oidx]) : 0.0f;
        }
    }
}

// ---------------------------------------------------------------------------
// launch
// ---------------------------------------------------------------------------
extern "C" void kernel_launch(void* const* d_in, const int* in_sizes, int n_in,
                              void* d_out, int out_size)
{
    const float* x      = (const float*)d_in[0];   // (B,L,T)
    const int*   mask   = (const int*)  d_in[1];   // (B,L)  [assumed int32]
    const float* bias   = (const float*)d_in[2];   // (B,L,L,H)
    const float* W_up   = (const float*)d_in[3];   // (E,T)
    const float* W_proj = (const float*)d_in[4];   // (2E,E)
    float* out = (float*)d_out;

    float* xe = nullptr;
    float* t  = nullptr;
    cudaGetSymbolAddress((void**)&xe, g_xe);
    cudaGetSymbolAddress((void**)&t,  g_t);

    // GEMM1: xe(1024,2560) = x(1024,1024) @ W_up(2560,1024)^T
    {
        dim3 grid(B_*L_ / BM, E_ / BN);
        gemm_tf32_kernel<<<grid, 256>>>(x, W_up, xe, B_*L_, E_, T_);
    }
    // GEMM2: t(1024,5120) = xe(1024,2560) @ W_proj(5120,2560)^T
    {
        dim3 grid(B_*L_ / BM, F_ / BN);
        gemm_tf32_kernel<<<grid, 256>>>(xe, W_proj, t, B_*L_, F_, E_);
    }
    // fused q.k^T + bias + mask epilogue
    {
        dim3 grid(L_ / 32, L_ / 32, B_);
        attn_epilogue_kernel<<<grid, 256>>>(t, mask, bias, out);
    }
}

// round 2
// speedup vs baseline: 1.0393x; 1.0393x over previous
#include <cuda_runtime.h>
#include <cstdint>

#define B_  2
#define L_  512
#define T_  1024
#define E_  2560
#define H_  128
#define HW_ 20
#define F_  (2*E_)   // 5120

// Scratch (no cudaMalloc allowed)
__device__ float g_xe[B_*L_*E_];   // (1024, 2560)  10 MB
__device__ float g_t [B_*L_*F_];   // (1024, 5120)  20 MB

// ---------------------------------------------------------------------------
// tf32 helpers
// ---------------------------------------------------------------------------
__device__ __forceinline__ uint32_t f2tf32(float x) {
    uint32_t r;
    asm("cvt.rna.tf32.f32 %0, %1;" : "=r"(r) : "f"(x));
    return r;
}

__device__ __forceinline__ void mma_tf32(float (&d)[4], const uint32_t (&a)[4],
                                         const uint32_t (&b)[2]) {
    asm volatile(
        "mma.sync.aligned.m16n8k8.row.col.f32.tf32.tf32.f32 "
        "{%0,%1,%2,%3}, {%4,%5,%6,%7}, {%8,%9}, {%0,%1,%2,%3};"
        : "+f"(d[0]), "+f"(d[1]), "+f"(d[2]), "+f"(d[3])
        : "r"(a[0]), "r"(a[1]), "r"(a[2]), "r"(a[3]), "r"(b[0]), "r"(b[1]));
}

__device__ __forceinline__ void cp_async16(uint32_t smem, const void* g) {
    asm volatile("cp.async.cg.shared.global [%0], [%1], 16;" :: "r"(smem), "l"(g));
}

// ---------------------------------------------------------------------------
// GEMM: C[M,N] = A[M,K] (row) * W[N,K]^T (W row-major N x K)
// 128x128x32 tiles, 8 warps (2m x 4n), warp tile 64x32, tf32 mma m16n8k8,
// 4-stage cp.async pipeline (prefetch distance 3), dynamic smem 147KB.
// ---------------------------------------------------------------------------
#define BM 128
#define BN 128
#define BK 32
#define STAGES 4
#define PADW 36   // row length in words (32 data + 4 pad) -> conflict-free frags

// dynamic smem layout: As[STAGES][BM][PADW] then Ws[STAGES][BN][PADW]
#define SMEM_MAT (BM * PADW)              // words per matrix per stage
#define SMEM_BYTES (STAGES * 2 * SMEM_MAT * 4)

extern __shared__ float smem_dyn[];

__global__ void __launch_bounds__(256, 1) gemm_tf32_kernel(
    const float* __restrict__ A, const float* __restrict__ W,
    float* __restrict__ C, int M, int N, int K)
{
    float* As = smem_dyn;                          // [STAGES][BM][PADW]
    float* Ws = smem_dyn + STAGES * SMEM_MAT;      // [STAGES][BN][PADW]

    const int tid  = threadIdx.x;
    const int warp = tid >> 5;
    const int lane = tid & 31;
    const int r = lane >> 2;      // 0..7
    const int c = lane & 3;       // 0..3
    const int wm = (warp >> 2) * 64;   // 0 / 64
    const int wn = (warp & 3) * 32;    // 0 / 32 / 64 / 96
    const int m0 = blockIdx.x * BM;
    const int n0 = blockIdx.y * BN;

    float acc[4][4][4];
    #pragma unroll
    for (int i = 0; i < 4; ++i)
        #pragma unroll
        for (int j = 0; j < 4; ++j)
            #pragma unroll
            for (int v = 0; v < 4; ++v) acc[i][j][v] = 0.0f;

    const int KT = K / BK;

    // loader thread mapping: row chunk = tid/8 (+32 per iter), v = tid%8 (float4 col)
    const int lm = tid >> 3;      // 0..31
    const int lv = (tid & 7) * 4; // 0,4,...,28

    // stage loader: per stage 128 rows x 8 float4 for A and W (8 cp.async/thread)
    #define LOAD_STAGE(st, kt)                                                   \
    {                                                                            \
        const int kbase = (kt) * BK;                                             \
        float* as = As + (st) * SMEM_MAT;                                        \
        float* ws = Ws + (st) * SMEM_MAT;                                        \
        _Pragma("unroll")                                                        \
        for (int i = 0; i < 4; ++i) {                                            \
            int m = lm + i * 32;                                                 \
            uint32_t da = (uint32_t)__cvta_generic_to_shared(&as[m*PADW + lv]);  \
            cp_async16(da, &A[(size_t)(m0 + m) * K + kbase + lv]);               \
            uint32_t dw = (uint32_t)__cvta_generic_to_shared(&ws[m*PADW + lv]);  \
            cp_async16(dw, &W[(size_t)(n0 + m) * K + kbase + lv]);               \
        }                                                                        \
        asm volatile("cp.async.commit_group;");                                  \
    }

    // prologue: fill STAGES-1 = 3 stages
    LOAD_STAGE(0, 0);
    LOAD_STAGE(1, 1);
    LOAD_STAGE(2, 2);

    for (int kt = 0; kt < KT; ++kt) {
        asm volatile("cp.async.wait_group 2;");
        __syncthreads();

        // prefetch stage kt+3 (overwrites stage consumed at kt-1)
        if (kt + 3 < KT) {
            LOAD_STAGE((kt + 3) & 3, kt + 3);
        } else {
            asm volatile("cp.async.commit_group;");   // keep group count uniform
        }

        const int st = kt & 3;
        const float* as = As + st * SMEM_MAT;
        const float* ws = Ws + st * SMEM_MAT;

        #pragma unroll
        for (int s = 0; s < 4; ++s) {
            uint32_t af[4][4], bf[4][2];
            #pragma unroll
            for (int i = 0; i < 4; ++i) {
                int m = wm + i * 16 + r;
                af[i][0] = f2tf32(as[m * PADW + s*8 + c    ]);
                af[i][1] = f2tf32(as[(m + 8) * PADW + s*8 + c]);
                af[i][2] = f2tf32(as[m * PADW + s*8 + c + 4]);
                af[i][3] = f2tf32(as[(m + 8) * PADW + s*8 + c + 4]);
            }
            #pragma unroll
            for (int j = 0; j < 4; ++j) {
                int n = wn + j * 8 + r;
                bf[j][0] = f2tf32(ws[n * PADW + s*8 + c    ]);
                bf[j][1] = f2tf32(ws[n * PADW + s*8 + c + 4]);
            }
            #pragma unroll
            for (int i = 0; i < 4; ++i)
                #pragma unroll
                for (int j = 0; j < 4; ++j)
                    mma_tf32(acc[i][j], af[i], bf[j]);
        }
        __syncthreads();
    }

    // epilogue
    #pragma unroll
    for (int i = 0; i < 4; ++i) {
        #pragma unroll
        for (int j = 0; j < 4; ++j) {
            int m = m0 + wm + i * 16 + r;
            int n = n0 + wn + j * 8 + 2 * c;
            C[(size_t)m * N + n]           = acc[i][j][0];
            C[(size_t)m * N + n + 1]       = acc[i][j][1];
            C[(size_t)(m + 8) * N + n]     = acc[i][j][2];
            C[(size_t)(m + 8) * N + n + 1] = acc[i][j][3];
        }
    }
    #undef LOAD_STAGE
}

// ---------------------------------------------------------------------------
// Fused epilogue:
//   t (1024, 5120) row (b,l): head h occupies cols [h*40, h*40+40);
//   q = cols [h*40, +20), k = cols [h*40+20, +20)
//   out[b,q,k,h] = mask[b,k] ? (q.k)*HW^-0.5 + bias[b,q,k,h] : 0
// ---------------------------------------------------------------------------
__global__ void __launch_bounds__(256) attn_epilogue_kernel(
    const float* __restrict__ t, const int* __restrict__ mask,
    const float* __restrict__ bias, float* __restrict__ out)
{
    __shared__ __align__(16) float qs[32][8][20];
    __shared__ __align__(16) float ks[32][8][20];

    const int b  = blockIdx.z;
    const int q0 = blockIdx.y * 32;
    const int k0 = blockIdx.x * 32;
    const int tid = threadIdx.x;
    const int kl = tid >> 3;   // 0..31
    const int hl = tid & 7;    // 0..7
    const float scale = 0.22360679774997896f;   // 20^-0.5

    const int maskv = mask[b * L_ + k0 + kl];

    for (int hc = 0; hc < H_ / 8; ++hc) {
        __syncthreads();   // protect smem reuse from previous iteration
        #pragma unroll
        for (int i = 0; i < 20; ++i) {
            int e   = tid + i * 256;       // 0..5119
            int qq  = e / 160;
            int rem = e - qq * 160;
            int hh  = rem / 20;
            int cc  = rem - hh * 20;
            int col = (hc * 8 + hh) * 40 + cc;
            qs[qq][hh][cc] = t[(size_t)(b * L_ + q0 + qq) * F_ + col];
            ks[qq][hh][cc] = t[(size_t)(b * L_ + k0 + qq) * F_ + col + 20];
        }
        __syncthreads();

        const float4 kv0 = *(const float4*)&ks[kl][hl][0];
        const float4 kv1 = *(const float4*)&ks[kl][hl][4];
        const float4 kv2 = *(const float4*)&ks[kl][hl][8];
        const float4 kv3 = *(const float4*)&ks[kl][hl][12];
        const float4 kv4 = *(const float4*)&ks[kl][hl][16];

        #pragma unroll 4
        for (int q = 0; q < 32; ++q) {
            const float* qr = &qs[q][hl][0];
            const float4 a0 = *(const float4*)&qr[0];
            const float4 a1 = *(const float4*)&qr[4];
            const float4 a2 = *(const float4*)&qr[8];
            const float4 a3 = *(const float4*)&qr[12];
            const float4 a4 = *(const float4*)&qr[16];
            float acc = a0.x*kv0.x + a0.y*kv0.y + a0.z*kv0.z + a0.w*kv0.w
                      + a1.x*kv1.x + a1.y*kv1.y + a1.z*kv1.z + a1.w*kv1.w
                      + a2.x*kv2.x + a2.y*kv2.y + a2.z*kv2.z + a2.w*kv2.w
                      + a3.x*kv3.x + a3.y*kv3.y + a3.z*kv3.z + a3.w*kv3.w
                      + a4.x*kv4.x + a4.y*kv4.y + a4.z*kv4.z + a4.w*kv4.w;
            size_t oidx = ((size_t)(b * L_ + q0 + q) * L_ + (k0 + kl)) * H_
                        + hc * 8 + hl;
            out[oidx] = maskv ? fmaf(acc, scale, bias[oidx]) : 0.0f;
        }
    }
}

// ---------------------------------------------------------------------------
// launch
// ---------------------------------------------------------------------------
extern "C" void kernel_launch(void* const* d_in, const int* in_sizes, int n_in,
                              void* d_out, int out_size)
{
    const float* x      = (const float*)d_in[0];   // (B,L,T)
    const int*   mask   = (const int*)  d_in[1];   // (B,L)  int32
    const float* bias   = (const float*)d_in[2];   // (B,L,L,H)
    const float* W_up   = (const float*)d_in[3];   // (E,T)
    const float* W_proj = (const float*)d_in[4];   // (2E,E)
    float* out = (float*)d_out;

    float* xe = nullptr;
    float* t  = nullptr;
    cudaGetSymbolAddress((void**)&xe, g_xe);
    cudaGetSymbolAddress((void**)&t,  g_t);

    // allow 147KB dynamic smem (idempotent)
    cudaFuncSetAttribute(gemm_tf32_kernel,
                         cudaFuncAttributeMaxDynamicSharedMemorySize, SMEM_BYTES);

    // GEMM1: xe(1024,2560) = x(1024,1024) @ W_up(2560,1024)^T
    {
        dim3 grid(B_*L_ / BM, E_ / BN);
        gemm_tf32_kernel<<<grid, 256, SMEM_BYTES>>>(x, W_up, xe, B_*L_, E_, T_);
    }
    // GEMM2: t(1024,5120) = xe(1024,2560) @ W_proj(5120,2560)^T
    {
        dim3 grid(B_*L_ / BM, F_ / BN);
        gemm_tf32_kernel<<<grid, 256, SMEM_BYTES>>>(xe, W_proj, t, B_*L_, F_, E_);
    }
    // fused q.k^T + bias + mask epilogue
    {
        dim3 grid(L_ / 32, L_ / 32, B_);
        attn_epilogue_kernel<<<grid, 256>>>(t, mask, bias, out);
    }
}

// round 4
// speedup vs baseline: 1.1503x; 1.1068x over previous
#include <cuda_runtime.h>
#include <cuda_fp16.h>
#include <cstdint>

#define B_  2
#define L_  512
#define T_  1024
#define E_  2560
#define H_  128
#define F_  (2*E_)   // 5120

// Scratch (no cudaMalloc allowed)
__device__ __half g_xh [B_*L_*T_];   // x in fp16        2 MB
__device__ __half g_wuh[E_*T_];      // W_up in fp16     5 MB
__device__ __half g_wph[F_*E_];      // W_proj in fp16   26 MB
__device__ __half g_xeh[B_*L_*E_];   // xe in fp16       5 MB
__device__ float  g_t  [B_*L_*F_];   // t (f32)          20 MB

// ---------------------------------------------------------------------------
// helpers
// ---------------------------------------------------------------------------
__device__ __forceinline__ uint32_t smem_u32(const void* p) {
    uint32_t a;
    asm("{ .reg .u64 t; cvta.to.shared.u64 t, %1; cvt.u32.u64 %0, t; }"
        : "=r"(a) : "l"(p));
    return a;
}

__device__ __forceinline__ void cp_async16(uint32_t smem, const void* g) {
    asm volatile("cp.async.cg.shared.global [%0], [%1], 16;" :: "r"(smem), "l"(g));
}

__device__ __forceinline__ void ldsm_x4(uint32_t (&r)[4], uint32_t addr) {
    asm volatile("ldmatrix.sync.aligned.m8n8.x4.shared.b16 {%0,%1,%2,%3}, [%4];"
                 : "=r"(r[0]), "=r"(r[1]), "=r"(r[2]), "=r"(r[3]) : "r"(addr));
}

__device__ __forceinline__ void mma_f16(float (&d)[4], const uint32_t (&a)[4],
                                        const uint32_t b0, const uint32_t b1) {
    asm volatile(
        "mma.sync.aligned.m16n8k16.row.col.f32.f16.f16.f32 "
        "{%0,%1,%2,%3}, {%4,%5,%6,%7}, {%8,%9}, {%0,%1,%2,%3};"
        : "+f"(d[0]), "+f"(d[1]), "+f"(d[2]), "+f"(d[3])
        : "r"(a[0]), "r"(a[1]), "r"(a[2]), "r"(a[3]), "r"(b0), "r"(b1));
}

// ---------------------------------------------------------------------------
// f32 -> f16 conversion (vectorized, grid-stride)
// ---------------------------------------------------------------------------
__global__ void f2h_kernel(const float4* __restrict__ in, uint2* __restrict__ out,
                           int n4)
{
    for (int i = blockIdx.x * blockDim.x + threadIdx.x; i < n4;
         i += gridDim.x * blockDim.x) {
        float4 v = in[i];
        __half2 lo = __floats2half2_rn(v.x, v.y);
        __half2 hi = __floats2half2_rn(v.z, v.w);
        uint2 o;
        o.x = *(const uint32_t*)&lo;
        o.y = *(const uint32_t*)&hi;
        out[i] = o;
    }
}

// ---------------------------------------------------------------------------
// fp16 GEMM: C[M,N] = A[M,K] (row, fp16) * W[N,K]^T (row, fp16)
// 128x128x32 tiles, 8 warps (2m x 4n), warp tile 64x32, mma m16n8k16,
// 4-stage cp.async, ldmatrix fragments, 80B row pitch (conflict-free).
// OutT = float or __half.
// ---------------------------------------------------------------------------
#define BM 128
#define BN 128
#define BK 32
#define STAGES 4
#define PADH 40                 // halves per row (32 data + 8 pad) = 80 B
#define ROWB (PADH*2)           // 80
#define MAT_BYTES (BM*ROWB)     // 10240 per matrix per stage
#define STG_BYTES (2*MAT_BYTES) // 20480
#define GSMEM_BYTES (STAGES*STG_BYTES)   // 81920

template <typename OutT>
__global__ void __launch_bounds__(256, 2) gemm_f16(
    const __half* __restrict__ A, const __half* __restrict__ W,
    OutT* __restrict__ C, int M, int N, int K)
{
    extern __shared__ __align__(16) char gsm[];
    const uint32_t sBase = smem_u32(gsm);

    const int tid  = threadIdx.x;
    const int warp = tid >> 5;
    const int lane = tid & 31;
    const int wm = (warp >> 2) * 64;
    const int wn = (warp & 3) * 32;
    const int m0 = blockIdx.x * BM;
    const int n0 = blockIdx.y * BN;

    float acc[4][4][4];
    #pragma unroll
    for (int i = 0; i < 4; ++i)
        #pragma unroll
        for (int j = 0; j < 4; ++j)
            #pragma unroll
            for (int v = 0; v < 4; ++v) acc[i][j][v] = 0.0f;

    const int KT = K / BK;

    // loader mapping: chunk = tid&3 (16B), row = tid>>2 (+64)
    const int lrow = tid >> 2;
    const int lch  = (tid & 3) * 8;    // halves offset within row

    #define LOAD_STAGE(st, kt)                                                  \
    {                                                                           \
        const int kb = (kt) * BK;                                               \
        const uint32_t as = sBase + (st) * STG_BYTES;                           \
        const uint32_t ws = as + MAT_BYTES;                                     \
        _Pragma("unroll")                                                       \
        for (int i = 0; i < 2; ++i) {                                           \
            int row = lrow + i * 64;                                            \
            cp_async16(as + row * ROWB + lch * 2,                               \
                       &A[(size_t)(m0 + row) * K + kb + lch]);                  \
            cp_async16(ws + row * ROWB + lch * 2,                               \
                       &W[(size_t)(n0 + row) * K + kb + lch]);                  \
        }                                                                       \
        asm volatile("cp.async.commit_group;");                                 \
    }

    LOAD_STAGE(0, 0);
    LOAD_STAGE(1, 1);
    LOAD_STAGE(2, 2);

    // ldmatrix lane addressing
    const int sel  = lane >> 3;          // 0..3
    const int lr8  = lane & 7;           // row within 8-group
    const int selR = (sel & 1) * 8;      // +8 rows for odd sel
    const int selK = (sel >> 1) * 16;    // +16 bytes (k half) for sel>=2

    for (int kt = 0; kt < KT; ++kt) {
        asm volatile("cp.async.wait_group 2;");
        __syncthreads();

        const int st = kt & 3;
        const uint32_t as = sBase + st * STG_BYTES;
        const uint32_t ws = as + MAT_BYTES;

        #pragma unroll
        for (int s = 0; s < 2; ++s) {        // two k16 steps per stage
            const int kbyte = s * 32 + selK;
            uint32_t af[4][4];
            #pragma unroll
            for (int i = 0; i < 4; ++i) {
                int m = wm + i * 16 + selR + lr8;
                ldsm_x4(af[i], as + m * ROWB + kbyte);
            }
            uint32_t bf[4][2];
            #pragma unroll
            for (int j2 = 0; j2 < 2; ++j2) { // two n16 groups
                uint32_t r[4];
                int n = wn + j2 * 16 + selR + lr8;
                ldsm_x4(r, ws + n * ROWB + kbyte);
                bf[j2*2][0]   = r[0]; bf[j2*2][1]   = r[2];
                bf[j2*2+1][0] = r[1]; bf[j2*2+1][1] = r[3];
            }
            #pragma unroll
            for (int i = 0; i < 4; ++i)
                #pragma unroll
                for (int j = 0; j < 4; ++j)
                    mma_f16(acc[i][j], af[i], bf[j][0], bf[j][1]);
        }
        __syncthreads();

        if (kt + 3 < KT) {
            LOAD_STAGE((kt + 3) & 3, kt + 3);
        } else {
            asm volatile("cp.async.commit_group;");
        }
    }

    // epilogue: thread (lane) holds c[0..1] at (m, n), c[2..3] at (m+8, n)
    const int er = lane >> 2;        // 0..7
    const int ec = (lane & 3) * 2;   // 0,2,4,6
    #pragma unroll
    for (int i = 0; i < 4; ++i) {
        #pragma unroll
        for (int j = 0; j < 4; ++j) {
            int m = m0 + wm + i * 16 + er;
            int n = n0 + wn + j * 8 + ec;
            if (sizeof(OutT) == 4) {
                float2 v0 = make_float2(acc[i][j][0], acc[i][j][1]);
                float2 v1 = make_float2(acc[i][j][2], acc[i][j][3]);
                *(float2*)((float*)C + (size_t)m * N + n)       = v0;
                *(float2*)((float*)C + (size_t)(m + 8) * N + n) = v1;
            } else {
                __half2 h0 = __floats2half2_rn(acc[i][j][0], acc[i][j][1]);
                __half2 h1 = __floats2half2_rn(acc[i][j][2], acc[i][j][3]);
                *(__half2*)((__half*)C + (size_t)m * N + n)       = h0;
                *(__half2*)((__half*)C + (size_t)(m + 8) * N + n) = h1;
            }
        }
    }
    #undef LOAD_STAGE
}

// ---------------------------------------------------------------------------
// Fused epilogue: f32x2 packed FMA over head-pairs, float2 bias/out IO.
//   t row (b,l): head h = cols [h*40, h*40+20) (q) / [h*40+20, h*40+40) (k)
//   out[b,q,k,h] = mask[b,k] ? (q.k)*20^-0.5 + bias[b,q,k,h] : 0
// Block: (b, 32 q, 32 k), 16 heads per iter (8 iters). 256 thr = (kl:32, hp:8).
// smem: [q/k][32 rows][8 hp][44]: word = row*352 + hp*44 + c*2 + j
// ---------------------------------------------------------------------------
#define EPW 11264
#define EP_SMEM_BYTES (2*EPW*4)

__global__ void __launch_bounds__(256) attn_epilogue_kernel(
    const float* __restrict__ t, const int* __restrict__ mask,
    const float* __restrict__ bias, float* __restrict__ out)
{
    extern __shared__ __align__(16) float esm[];
    float* qs = esm;
    float* ks = esm + EPW;

    const int b  = blockIdx.z;
    const int q0 = blockIdx.y * 32;
    const int k0 = blockIdx.x * 32;
    const int tid = threadIdx.x;
    const int kl = tid >> 3;
    const int hp = tid & 7;
    const float scale = 0.22360679774997896f;

    const int maskv = mask[b * L_ + k0 + kl];
    const size_t qrow = (size_t)(b * L_ + q0) * F_;
    const size_t krow = (size_t)(b * L_ + k0) * F_;

    for (int hc = 0; hc < 8; ++hc) {
        __syncthreads();
        #pragma unroll
        for (int i = 0; i < 40; ++i) {
            int e   = tid + i * 256;
            int q   = e / 320;
            int rem = e - q * 320;
            int h16 = rem / 20;
            int c   = rem - h16 * 20;
            int dw  = q * 352 + (h16 >> 1) * 44 + c * 2 + (h16 & 1);
            int col = (hc * 16 + h16) * 40 + c;
            qs[dw] = t[qrow + (size_t)q * F_ + col];
            ks[dw] = t[krow + (size_t)q * F_ + col + 20];
        }
        __syncthreads();

        ulonglong2 kv[10];
        {
            const ulonglong2* kp = (const ulonglong2*)&ks[kl * 352 + hp * 44];
            #pragma unroll
            for (int i = 0; i < 10; ++i) kv[i] = kp[i];
        }
        const float* qb = &qs[hp * 44];
        const size_t obase = ((size_t)(b * L_ + q0) * L_ + k0 + kl) * H_
                           + hc * 16 + hp * 2;

        #pragma unroll 4
        for (int q = 0; q < 32; ++q) {
            const ulonglong2* qp = (const ulonglong2*)&qb[q * 352];
            unsigned long long acc0 = 0ull, acc1 = 0ull;
            #pragma unroll
            for (int i = 0; i < 10; ++i) {
                ulonglong2 qv = qp[i];
                asm("fma.rn.f32x2 %0, %1, %2, %0;" : "+l"(acc0) : "l"(qv.x), "l"(kv[i].x));
                asm("fma.rn.f32x2 %0, %1, %2, %0;" : "+l"(acc1) : "l"(qv.y), "l"(kv[i].y));
            }
            float l0, h0, l1, h1;
            asm("mov.b64 {%0,%1}, %2;" : "=f"(l0), "=f"(h0) : "l"(acc0));
            asm("mov.b64 {%0,%1}, %2;" : "=f"(l1), "=f"(h1) : "l"(acc1));
            float d0 = l0 + l1;
            float d1 = h0 + h1;

            size_t oidx = obase + (size_t)q * (L_ * H_);
            float2 bv = *(const float2*)&bias[oidx];
            float2 ov;
            ov.x = maskv ? fmaf(d0, scale, bv.x) : 0.0f;
            ov.y = maskv ? fmaf(d1, scale, bv.y) : 0.0f;
            *(float2*)&out[oidx] = ov;
        }
    }
}

// ---------------------------------------------------------------------------
// launch
// ---------------------------------------------------------------------------
extern "C" void kernel_launch(void* const* d_in, const int* in_sizes, int n_in,
                              void* d_out, int out_size)
{
    const float* x      = (const float*)d_in[0];   // (B,L,T)
    const int*   mask   = (const int*)  d_in[1];   // (B,L)  int32
    const float* bias   = (const float*)d_in[2];   // (B,L,L,H)
    const float* W_up   = (const float*)d_in[3];   // (E,T)
    const float* W_proj = (const float*)d_in[4];   // (2E,E)
    float* out = (float*)d_out;

    __half *xh, *wuh, *wph, *xeh;
    float* t;
    cudaGetSymbolAddress((void**)&xh,  g_xh);
    cudaGetSymbolAddress((void**)&wuh, g_wuh);
    cudaGetSymbolAddress((void**)&wph, g_wph);
    cudaGetSymbolAddress((void**)&xeh, g_xeh);
    cudaGetSymbolAddress((void**)&t,   g_t);

    cudaFuncSetAttribute(gemm_f16<float>,
                         cudaFuncAttributeMaxDynamicSharedMemorySize, GSMEM_BYTES);
    cudaFuncSetAttribute(gemm_f16<__half>,
                         cudaFuncAttributeMaxDynamicSharedMemorySize, GSMEM_BYTES);
    cudaFuncSetAttribute(attn_epilogue_kernel,
                         cudaFuncAttributeMaxDynamicSharedMemorySize, EP_SMEM_BYTES);

    // f32 -> f16 conversions
    f2h_kernel<<<512,  256>>>((const float4*)x,      (uint2*)xh,  B_*L_*T_/4);
    f2h_kernel<<<1024, 256>>>((const float4*)W_up,   (uint2*)wuh, E_*T_/4);
    f2h_kernel<<<2048, 256>>>((const float4*)W_proj, (uint2*)wph, F_*E_/4);

    // GEMM1: xe_h(1024,2560) = x_h @ W_up_h^T   (fp16 out)
    {
        dim3 grid(B_*L_ / BM, E_ / BN);
        gemm_f16<__half><<<grid, 256, GSMEM_BYTES>>>(xh, wuh, xeh, B_*L_, E_, T_);
    }
    // GEMM2: t(1024,5120) = xe_h @ W_proj_h^T   (f32 out)
    {
        dim3 grid(B_*L_ / BM, F_ / BN);
        gemm_f16<float><<<grid, 256, GSMEM_BYTES>>>(xeh, wph, t, B_*L_, F_, E_);
    }
    // fused q.k^T + bias + mask epilogue
    {
        dim3 grid(L_ / 32, L_ / 32, B_);
        attn_epilogue_kernel<<<grid, 256, EP_SMEM_BYTES>>>(t, mask, bias, out);
    }
}

// round 6
// speedup vs baseline: 1.2449x; 1.0822x over previous
#include <cuda_runtime.h>
#include <cuda_fp16.h>
#include <cstdint>

#define B_  2
#define L_  512
#define T_  1024
#define E_  2560
#define H_  128
#define F_  (2*E_)   // 5120
#define TSH 48       // halves per (l,h) in ts: q[20] pad[4] k[20] pad[4]

// Scratch (no cudaMalloc allowed)
__device__ __half g_xh [B_*L_*T_];      // x fp16        2 MB
__device__ __half g_wuh[E_*T_];         // W_up fp16     5 MB
__device__ __half g_wph[F_*E_];         // W_proj fp16   26 MB
__device__ __half g_xeh[B_*L_*E_];      // xe fp16       5 MB
__device__ __half g_ts [B_*L_*H_*TSH]; // split q|k fp16 12.6 MB

// ---------------------------------------------------------------------------
// helpers
// ---------------------------------------------------------------------------
__device__ __forceinline__ uint32_t smem_u32(const void* p) {
    uint32_t a;
    asm("{ .reg .u64 t; cvta.to.shared.u64 t, %1; cvt.u32.u64 %0, t; }"
        : "=r"(a) : "l"(p));
    return a;
}

__device__ __forceinline__ void cp_async16(uint32_t smem, const void* g) {
    asm volatile("cp.async.cg.shared.global [%0], [%1], 16;" :: "r"(smem), "l"(g));
}

__device__ __forceinline__ void ldsm_x4(uint32_t (&r)[4], uint32_t addr) {
    asm volatile("ldmatrix.sync.aligned.m8n8.x4.shared.b16 {%0,%1,%2,%3}, [%4];"
                 : "=r"(r[0]), "=r"(r[1]), "=r"(r[2]), "=r"(r[3]) : "r"(addr));
}

__device__ __forceinline__ void mma_f16(float (&d)[4], const uint32_t (&a)[4],
                                        const uint32_t b0, const uint32_t b1) {
    asm volatile(
        "mma.sync.aligned.m16n8k16.row.col.f32.f16.f16.f32 "
        "{%0,%1,%2,%3}, {%4,%5,%6,%7}, {%8,%9}, {%0,%1,%2,%3};"
        : "+f"(d[0]), "+f"(d[1]), "+f"(d[2]), "+f"(d[3])
        : "r"(a[0]), "r"(a[1]), "r"(a[2]), "r"(a[3]), "r"(b0), "r"(b1));
}

// ---------------------------------------------------------------------------
// f32 -> f16 conversion (vectorized, grid-stride)
// ---------------------------------------------------------------------------
__global__ void f2h_kernel(const float4* __restrict__ in, uint2* __restrict__ out,
                           int n4)
{
    for (int i = blockIdx.x * blockDim.x + threadIdx.x; i < n4;
         i += gridDim.x * blockDim.x) {
        float4 v = in[i];
        __half2 lo = __floats2half2_rn(v.x, v.y);
        __half2 hi = __floats2half2_rn(v.z, v.w);
        uint2 o;
        o.x = *(const uint32_t*)&lo;
        o.y = *(const uint32_t*)&hi;
        out[i] = o;
    }
}

// ---------------------------------------------------------------------------
// fp16 GEMM: C[M,N] = A[M,K] * W[N,K]^T, 128x128x32 tiles, 4-stage cp.async.
// MODE 0: plain __half row-major out.
// MODE 2: split-ts out: col n -> head h=n/40, c=n%40; c<20 -> q slot (scaled
//         by 20^-0.5) at pos c, else k slot at pos c+4; row m -> ts[m][h][48].
// ---------------------------------------------------------------------------
#define BM 128
#define BN 128
#define BK 32
#define STAGES 4
#define PADH 40
#define ROWB (PADH*2)
#define MAT_BYTES (BM*ROWB)
#define STG_BYTES (2*MAT_BYTES)
#define GSMEM_BYTES (STAGES*STG_BYTES)   // 81920

template <int MODE>
__global__ void __launch_bounds__(256, 2) gemm_f16(
    const __half* __restrict__ A, const __half* __restrict__ W,
    __half* __restrict__ C, int M, int N, int K)
{
    extern __shared__ __align__(16) char gsm[];
    const uint32_t sBase = smem_u32(gsm);

    const int tid  = threadIdx.x;
    const int warp = tid >> 5;
    const int lane = tid & 31;
    const int wm = (warp >> 2) * 64;
    const int wn = (warp & 3) * 32;
    const int m0 = blockIdx.x * BM;
    const int n0 = blockIdx.y * BN;

    float acc[4][4][4];
    #pragma unroll
    for (int i = 0; i < 4; ++i)
        #pragma unroll
        for (int j = 0; j < 4; ++j)
            #pragma unroll
            for (int v = 0; v < 4; ++v) acc[i][j][v] = 0.0f;

    const int KT = K / BK;
    const int lrow = tid >> 2;
    const int lch  = (tid & 3) * 8;

    #define LOAD_STAGE(st, kt)                                                  \
    {                                                                           \
        const int kb = (kt) * BK;                                               \
        const uint32_t as = sBase + (st) * STG_BYTES;                           \
        const uint32_t ws = as + MAT_BYTES;                                     \
        _Pragma("unroll")                                                       \
        for (int i = 0; i < 2; ++i) {                                           \
            int row = lrow + i * 64;                                            \
            cp_async16(as + row * ROWB + lch * 2,                               \
                       &A[(size_t)(m0 + row) * K + kb + lch]);                  \
            cp_async16(ws + row * ROWB + lch * 2,                               \
                       &W[(size_t)(n0 + row) * K + kb + lch]);                  \
        }                                                                       \
        asm volatile("cp.async.commit_group;");                                 \
    }

    LOAD_STAGE(0, 0);
    LOAD_STAGE(1, 1);
    LOAD_STAGE(2, 2);

    const int sel  = lane >> 3;
    const int lr8  = lane & 7;
    const int selR = (sel & 1) * 8;
    const int selK = (sel >> 1) * 16;

    for (int kt = 0; kt < KT; ++kt) {
        asm volatile("cp.async.wait_group 2;");
        __syncthreads();

        const int st = kt & 3;
        const uint32_t as = sBase + st * STG_BYTES;
        const uint32_t ws = as + MAT_BYTES;

        #pragma unroll
        for (int s = 0; s < 2; ++s) {
            const int kbyte = s * 32 + selK;
            uint32_t af[4][4];
            #pragma unroll
            for (int i = 0; i < 4; ++i) {
                int m = wm + i * 16 + selR + lr8;
                ldsm_x4(af[i], as + m * ROWB + kbyte);
            }
            uint32_t bf[4][2];
            #pragma unroll
            for (int j2 = 0; j2 < 2; ++j2) {
                uint32_t r[4];
                int n = wn + j2 * 16 + selR + lr8;
                ldsm_x4(r, ws + n * ROWB + kbyte);
                bf[j2*2][0]   = r[0]; bf[j2*2][1]   = r[2];
                bf[j2*2+1][0] = r[1]; bf[j2*2+1][1] = r[3];
            }
            #pragma unroll
            for (int i = 0; i < 4; ++i)
                #pragma unroll
                for (int j = 0; j < 4; ++j)
                    mma_f16(acc[i][j], af[i], bf[j][0], bf[j][1]);
        }
        __syncthreads();

        if (kt + 3 < KT) {
            LOAD_STAGE((kt + 3) & 3, kt + 3);
        } else {
            asm volatile("cp.async.commit_group;");
        }
    }

    const int er = lane >> 2;
    const int ec = (lane & 3) * 2;
    #pragma unroll
    for (int i = 0; i < 4; ++i) {
        #pragma unroll
        for (int j = 0; j < 4; ++j) {
            int m = m0 + wm + i * 16 + er;
            int n = n0 + wn + j * 8 + ec;
            if (MODE == 0) {
                __half2 h0 = __floats2half2_rn(acc[i][j][0], acc[i][j][1]);
                __half2 h1 = __floats2half2_rn(acc[i][j][2], acc[i][j][3]);
                *(__half2*)(C + (size_t)m * N + n)       = h0;
                *(__half2*)(C + (size_t)(m + 8) * N + n) = h1;
            } else {
                int h  = n / 40;
                int cc = n % 40;
                bool isq = cc < 20;
                int pos = isq ? cc : cc + 4;
                float s = isq ? 0.22360679774997896f : 1.0f;
                __half2 h0 = __floats2half2_rn(acc[i][j][0] * s, acc[i][j][1] * s);
                __half2 h1 = __floats2half2_rn(acc[i][j][2] * s, acc[i][j][3] * s);
                *(__half2*)(C + ((size_t)m * H_ + h) * TSH + pos)       = h0;
                *(__half2*)(C + ((size_t)(m + 8) * H_ + h) * TSH + pos) = h1;
            }
        }
    }
    #undef LOAD_STAGE
}

// ---------------------------------------------------------------------------
// Epilogue v3: out[b,q,k,h] = mask[b,k] ? q_h.k_h + bias[b,q,k,h] : 0
// (q pre-scaled in ts). Block: (b, 32q, 32k); 16 iters of 8 heads.
// smem: per array 8 planes of 772 f32 (plane h: 32 rows * 24); conflict-free.
// Fill: 256 segments (32 rows x 8 heads) per array; 1 segment/thread for q
// and 1 for k. Thread compute mapping: hpair=tid&3, kl=(tid>>2)&31, qhalf=tid>>7.
// ---------------------------------------------------------------------------
#define PLANE 772
#define EP_WORDS (2*8*PLANE)             // 12352 f32
#define EP_SMEM_BYTES (EP_WORDS*4)       // 49408

__global__ void __launch_bounds__(256) attn_epilogue_kernel(
    const __half* __restrict__ ts, const int* __restrict__ mask,
    const float* __restrict__ bias, float* __restrict__ out)
{
    extern __shared__ __align__(16) float esm[];
    float* qs = esm;
    float* ks = esm + 8 * PLANE;

    const int b  = blockIdx.z;
    const int q0 = blockIdx.y * 32;
    const int k0 = blockIdx.x * 32;
    const int tid = threadIdx.x;
    const int hpair  = tid & 3;
    const int kl     = (tid >> 2) & 31;
    const int qhalf  = tid >> 7;

    // fill mapping: one (row, head) segment per thread, for q and for k
    const int frow = tid >> 3;   // 0..31
    const int fh   = tid & 7;    // 0..7

    const int maskv = mask[b * L_ + k0 + kl];

    for (int hc = 0; hc < 16; ++hc) {
        const int h0 = hc * 8;
        __syncthreads();

        {
            const __half* qsrc = ts + ((size_t)(b * L_ + q0 + frow) * H_ + h0 + fh) * TSH;
            const __half* ksrc = ts + ((size_t)(b * L_ + k0 + frow) * H_ + h0 + fh) * TSH + 24;
            float* qdst = qs + fh * PLANE + frow * 24;
            float* kdst = ks + fh * PLANE + frow * 24;
            #pragma unroll
            for (int u = 0; u < 3; ++u) {
                uint4 vq = *(const uint4*)(qsrc + u * 8);
                uint4 vk = *(const uint4*)(ksrc + u * 8);
                const __half2* hq = (const __half2*)&vq;
                const __half2* hk = (const __half2*)&vk;
                float2 q0f = __half22float2(hq[0]), q1f = __half22float2(hq[1]);
                float2 q2f = __half22float2(hq[2]), q3f = __half22float2(hq[3]);
                float2 k0f = __half22float2(hk[0]), k1f = __half22float2(hk[1]);
                float2 k2f = __half22float2(hk[2]), k3f = __half22float2(hk[3]);
                *(float4*)(qdst + u * 8)     = make_float4(q0f.x, q0f.y, q1f.x, q1f.y);
                *(float4*)(qdst + u * 8 + 4) = make_float4(q2f.x, q2f.y, q3f.x, q3f.y);
                *(float4*)(kdst + u * 8)     = make_float4(k0f.x, k0f.y, k1f.x, k1f.y);
                *(float4*)(kdst + u * 8 + 4) = make_float4(k2f.x, k2f.y, k3f.x, k3f.y);
            }
        }
        __syncthreads();

        // k vectors for this thread's 2 heads
        float kv0[20], kv1[20];
        {
            const float* k0p = ks + (2 * hpair) * PLANE + kl * 24;
            const float* k1p = k0p + PLANE;
            #pragma unroll
            for (int u = 0; u < 5; ++u) {
                *(float4*)&kv0[u * 4] = *(const float4*)(k0p + u * 4);
                *(float4*)&kv1[u * 4] = *(const float4*)(k1p + u * 4);
            }
        }

        const float* qp0base = qs + (2 * hpair) * PLANE + (qhalf * 16) * 24;
        size_t ob = ((size_t)(b * L_ + q0 + qhalf * 16) * L_ + k0 + kl) * H_
                  + h0 + 2 * hpair;

        #pragma unroll 2
        for (int q = 0; q < 16; ++q) {
            const float* qv0 = qp0base + q * 24;
            const float* qv1 = qv0 + PLANE;
            float a0 = 0.f, a1 = 0.f, b0 = 0.f, b1 = 0.f;
            #pragma unroll
            for (int u = 0; u < 5; ++u) {
                float4 x0 = *(const float4*)(qv0 + u * 4);
                float4 x1 = *(const float4*)(qv1 + u * 4);
                a0 = fmaf(x0.x, kv0[u*4+0], a0); b0 = fmaf(x0.y, kv0[u*4+1], b0);
                a0 = fmaf(x0.z, kv0[u*4+2], a0); b0 = fmaf(x0.w, kv0[u*4+3], b0);
                a1 = fmaf(x1.x, kv1[u*4+0], a1); b1 = fmaf(x1.y, kv1[u*4+1], b1);
                a1 = fmaf(x1.z, kv1[u*4+2], a1); b1 = fmaf(x1.w, kv1[u*4+3], b1);
            }
            float d0 = a0 + b0;
            float d1 = a1 + b1;

            size_t oidx = ob + (size_t)q * (L_ * H_);
            float2 bv = *(const float2*)&bias[oidx];
            float2 ov;
            ov.x = maskv ? (d0 + bv.x) : 0.0f;
            ov.y = maskv ? (d1 + bv.y) : 0.0f;
            *(float2*)&out[oidx] = ov;
        }
    }
}

// ---------------------------------------------------------------------------
// launch
// ---------------------------------------------------------------------------
extern "C" void kernel_launch(void* const* d_in, const int* in_sizes, int n_in,
                              void* d_out, int out_size)
{
    const float* x      = (const float*)d_in[0];   // (B,L,T)
    const int*   mask   = (const int*)  d_in[1];   // (B,L) int32
    const float* bias   = (const float*)d_in[2];   // (B,L,L,H)
    const float* W_up   = (const float*)d_in[3];   // (E,T)
    const float* W_proj = (const float*)d_in[4];   // (2E,E)
    float* out = (float*)d_out;

    __half *xh, *wuh, *wph, *xeh, *ts;
    cudaGetSymbolAddress((void**)&xh,  g_xh);
    cudaGetSymbolAddress((void**)&wuh, g_wuh);
    cudaGetSymbolAddress((void**)&wph, g_wph);
    cudaGetSymbolAddress((void**)&xeh, g_xeh);
    cudaGetSymbolAddress((void**)&ts,  g_ts);

    cudaFuncSetAttribute(gemm_f16<0>,
                         cudaFuncAttributeMaxDynamicSharedMemorySize, GSMEM_BYTES);
    cudaFuncSetAttribute(gemm_f16<2>,
                         cudaFuncAttributeMaxDynamicSharedMemorySize, GSMEM_BYTES);
    cudaFuncSetAttribute(attn_epilogue_kernel,
                         cudaFuncAttributeMaxDynamicSharedMemorySize, EP_SMEM_BYTES);

    // f32 -> f16 conversions
    f2h_kernel<<<512,  256>>>((const float4*)x,      (uint2*)xh,  B_*L_*T_/4);
    f2h_kernel<<<1024, 256>>>((const float4*)W_up,   (uint2*)wuh, E_*T_/4);
    f2h_kernel<<<2048, 256>>>((const float4*)W_proj, (uint2*)wph, F_*E_/4);

    // GEMM1: xe_h(1024,2560) = x_h @ W_up_h^T
    {
        dim3 grid(B_*L_ / BM, E_ / BN);
        gemm_f16<0><<<grid, 256, GSMEM_BYTES>>>(xh, wuh, xeh, B_*L_, E_, T_);
    }
    // GEMM2: ts split layout = xe_h @ W_proj_h^T
    {
        dim3 grid(B_*L_ / BM, F_ / BN);
        gemm_f16<2><<<grid, 256, GSMEM_BYTES>>>(xeh, wph, ts, B_*L_, F_, E_);
    }
    // fused q.k^T + bias + mask epilogue
    {
        dim3 grid(L_ / 32, L_ / 32, B_);
        attn_epilogue_kernel<<<grid, 256, EP_SMEM_BYTES>>>(ts, mask, bias, out);
    }
}

// round 7
// speedup vs baseline: 1.9145x; 1.5378x over previous
#include <cuda_runtime.h>
#include <cuda_fp16.h>
#include <cstdint>

#define B_  2
#define L_  512
#define T_  1024
#define E_  2560
#define H_  128
#define F_  (2*E_)   // 5120
#define TSH 48       // halves per (l,h) in ts: q[20] pad[4] k[20] pad[4]

// Scratch (no cudaMalloc allowed)
__device__ __half g_xh [B_*L_*T_];      // x fp16        2 MB
__device__ __half g_wuh[E_*T_];         // W_up fp16     5 MB
__device__ __half g_wph[F_*E_];         // W_proj fp16   26 MB
__device__ __half g_xeh[B_*L_*E_];      // xe fp16       5 MB
__device__ __half g_ts [B_*L_*H_*TSH]; // split q|k fp16 12.6 MB

// ---------------------------------------------------------------------------
// helpers
// ---------------------------------------------------------------------------
__device__ __forceinline__ uint32_t smem_u32(const void* p) {
    uint32_t a;
    asm("{ .reg .u64 t; cvta.to.shared.u64 t, %1; cvt.u32.u64 %0, t; }"
        : "=r"(a) : "l"(p));
    return a;
}

__device__ __forceinline__ void cp_async16(uint32_t smem, const void* g) {
    asm volatile("cp.async.cg.shared.global [%0], [%1], 16;" :: "r"(smem), "l"(g));
}

__device__ __forceinline__ void ldsm_x4(uint32_t (&r)[4], uint32_t addr) {
    asm volatile("ldmatrix.sync.aligned.m8n8.x4.shared.b16 {%0,%1,%2,%3}, [%4];"
                 : "=r"(r[0]), "=r"(r[1]), "=r"(r[2]), "=r"(r[3]) : "r"(addr));
}

__device__ __forceinline__ void mma_f16(float (&d)[4], const uint32_t (&a)[4],
                                        const uint32_t b0, const uint32_t b1) {
    asm volatile(
        "mma.sync.aligned.m16n8k16.row.col.f32.f16.f16.f32 "
        "{%0,%1,%2,%3}, {%4,%5,%6,%7}, {%8,%9}, {%0,%1,%2,%3};"
        : "+f"(d[0]), "+f"(d[1]), "+f"(d[2]), "+f"(d[3])
        : "r"(a[0]), "r"(a[1]), "r"(a[2]), "r"(a[3]), "r"(b0), "r"(b1));
}

// ---------------------------------------------------------------------------
// f32 -> f16 conversion (vectorized, grid-stride)
// ---------------------------------------------------------------------------
__global__ void f2h_kernel(const float4* __restrict__ in, uint2* __restrict__ out,
                           int n4)
{
    for (int i = blockIdx.x * blockDim.x + threadIdx.x; i < n4;
         i += gridDim.x * blockDim.x) {
        float4 v = in[i];
        __half2 lo = __floats2half2_rn(v.x, v.y);
        __half2 hi = __floats2half2_rn(v.z, v.w);
        uint2 o;
        o.x = *(const uint32_t*)&lo;
        o.y = *(const uint32_t*)&hi;
        out[i] = o;
    }
}

// ---------------------------------------------------------------------------
// fp16 GEMM: C[M,N] = A[M,K] * W[N,K]^T, 128x128x32 tiles, 4-stage cp.async.
// MODE 0: plain __half row-major out.
// MODE 2: split-ts out: col n -> head h=n/40, c=n%40; c<20 -> q slot (scaled
//         by 20^-0.5) at pos c, else k slot at pos c+4; row m -> ts[m][h][48].
// ---------------------------------------------------------------------------
#define BM 128
#define BN 128
#define BK 32
#define STAGES 4
#define PADH 40
#define ROWB (PADH*2)
#define MAT_BYTES (BM*ROWB)
#define STG_BYTES (2*MAT_BYTES)
#define GSMEM_BYTES (STAGES*STG_BYTES)   // 81920

template <int MODE>
__global__ void __launch_bounds__(256, 2) gemm_f16(
    const __half* __restrict__ A, const __half* __restrict__ W,
    __half* __restrict__ C, int M, int N, int K)
{
    extern __shared__ __align__(16) char gsm[];
    const uint32_t sBase = smem_u32(gsm);

    const int tid  = threadIdx.x;
    const int warp = tid >> 5;
    const int lane = tid & 31;
    const int wm = (warp >> 2) * 64;
    const int wn = (warp & 3) * 32;
    const int m0 = blockIdx.x * BM;
    const int n0 = blockIdx.y * BN;

    float acc[4][4][4];
    #pragma unroll
    for (int i = 0; i < 4; ++i)
        #pragma unroll
        for (int j = 0; j < 4; ++j)
            #pragma unroll
            for (int v = 0; v < 4; ++v) acc[i][j][v] = 0.0f;

    const int KT = K / BK;
    const int lrow = tid >> 2;
    const int lch  = (tid & 3) * 8;

    #define LOAD_STAGE(st, kt)                                                  \
    {                                                                           \
        const int kb = (kt) * BK;                                               \
        const uint32_t as = sBase + (st) * STG_BYTES;                           \
        const uint32_t ws = as + MAT_BYTES;                                     \
        _Pragma("unroll")                                                       \
        for (int i = 0; i < 2; ++i) {                                           \
            int row = lrow + i * 64;                                            \
            cp_async16(as + row * ROWB + lch * 2,                               \
                       &A[(size_t)(m0 + row) * K + kb + lch]);                  \
            cp_async16(ws + row * ROWB + lch * 2,                               \
                       &W[(size_t)(n0 + row) * K + kb + lch]);                  \
        }                                                                       \
        asm volatile("cp.async.commit_group;");                                 \
    }

    LOAD_STAGE(0, 0);
    LOAD_STAGE(1, 1);
    LOAD_STAGE(2, 2);

    const int sel  = lane >> 3;
    const int lr8  = lane & 7;
    const int selR = (sel & 1) * 8;
    const int selK = (sel >> 1) * 16;

    for (int kt = 0; kt < KT; ++kt) {
        asm volatile("cp.async.wait_group 2;");
        __syncthreads();

        const int st = kt & 3;
        const uint32_t as = sBase + st * STG_BYTES;
        const uint32_t ws = as + MAT_BYTES;

        #pragma unroll
        for (int s = 0; s < 2; ++s) {
            const int kbyte = s * 32 + selK;
            uint32_t af[4][4];
            #pragma unroll
            for (int i = 0; i < 4; ++i) {
                int m = wm + i * 16 + selR + lr8;
                ldsm_x4(af[i], as + m * ROWB + kbyte);
            }
            uint32_t bf[4][2];
            #pragma unroll
            for (int j2 = 0; j2 < 2; ++j2) {
                uint32_t r[4];
                int n = wn + j2 * 16 + selR + lr8;
                ldsm_x4(r, ws + n * ROWB + kbyte);
                bf[j2*2][0]   = r[0]; bf[j2*2][1]   = r[2];
                bf[j2*2+1][0] = r[1]; bf[j2*2+1][1] = r[3];
            }
            #pragma unroll
            for (int i = 0; i < 4; ++i)
                #pragma unroll
                for (int j = 0; j < 4; ++j)
                    mma_f16(acc[i][j], af[i], bf[j][0], bf[j][1]);
        }
        __syncthreads();

        if (kt + 3 < KT) {
            LOAD_STAGE((kt + 3) & 3, kt + 3);
        } else {
            asm volatile("cp.async.commit_group;");
        }
    }

    const int er = lane >> 2;
    const int ec = (lane & 3) * 2;
    #pragma unroll
    for (int i = 0; i < 4; ++i) {
        #pragma unroll
        for (int j = 0; j < 4; ++j) {
            int m = m0 + wm + i * 16 + er;
            int n = n0 + wn + j * 8 + ec;
            if (MODE == 0) {
                __half2 h0 = __floats2half2_rn(acc[i][j][0], acc[i][j][1]);
                __half2 h1 = __floats2half2_rn(acc[i][j][2], acc[i][j][3]);
                *(__half2*)(C + (size_t)m * N + n)       = h0;
                *(__half2*)(C + (size_t)(m + 8) * N + n) = h1;
            } else {
                int h  = n / 40;
                int cc = n % 40;
                bool isq = cc < 20;
                int pos = isq ? cc : cc + 4;
                float s = isq ? 0.22360679774997896f : 1.0f;
                __half2 h0 = __floats2half2_rn(acc[i][j][0] * s, acc[i][j][1] * s);
                __half2 h1 = __floats2half2_rn(acc[i][j][2] * s, acc[i][j][3] * s);
                *(__half2*)(C + ((size_t)m * H_ + h) * TSH + pos)       = h0;
                *(__half2*)(C + ((size_t)(m + 8) * H_ + h) * TSH + pos) = h1;
            }
        }
    }
    #undef LOAD_STAGE
}

// ---------------------------------------------------------------------------
// Epilogue v4: out[b,q,k,h] = mask[b,k] ? q_h.k_h + bias[b,q,k,h] : 0
// (q pre-scaled in ts). Block: (b, 32q, 32k); 16 iters of 8 heads.
// Thread: h = tid&7, qg = (tid>>3)&7 (4 q rows), kg = tid>>6 (8 k rows).
// q held in REGISTERS (direct gmem load); only k staged in smem
// (8 planes x 772 f32, stride 772 === 4 mod 32 -> conflict-free broadcast).
// mask is warp-uniform per kk -> skip k load + 80 FMA + bias read when 0.
// ---------------------------------------------------------------------------
#define PLANE 772
#define EPK_WORDS (8*PLANE)   // 6176 f32 = 24704 B

__global__ void __launch_bounds__(256, 2) attn_epilogue_kernel(
    const __half* __restrict__ ts, const int* __restrict__ mask,
    const float* __restrict__ bias, float* __restrict__ out)
{
    __shared__ __align__(16) float ks[EPK_WORDS];

    const int b  = blockIdx.z;
    const int q0 = blockIdx.y * 32;
    const int k0 = blockIdx.x * 32;
    const int tid = threadIdx.x;
    const int h  = tid & 7;
    const int qg = (tid >> 3) & 7;   // 4 q rows each
    const int kg = tid >> 6;         // 8 k rows each (warp-uniform)
    const int frow = tid >> 3;       // fill: 0..31
    const int fh   = tid & 7;        // fill: 0..7

    int maskr[8];
    #pragma unroll
    for (int kk = 0; kk < 8; ++kk)
        maskr[kk] = mask[b * L_ + k0 + kg * 8 + kk];

    const size_t qrow_base = (size_t)(b * L_ + q0 + qg * 4) * H_;
    const size_t krow_base = (size_t)(b * L_ + k0 + frow) * H_;

    for (int hc = 0; hc < 16; ++hc) {
        const int h0 = hc * 8;
        __syncthreads();   // previous iteration's consumers done with ks

        // fill k plane: one (row, head) segment per thread, 24 halves -> f32
        {
            const __half* ksrc = ts + (krow_base + h0 + fh) * TSH + 24;
            float* kdst = ks + fh * PLANE + frow * 24;
            #pragma unroll
            for (int u = 0; u < 3; ++u) {
                uint4 vk = *(const uint4*)(ksrc + u * 8);
                const __half2* hk = (const __half2*)&vk;
                float2 f0 = __half22float2(hk[0]), f1 = __half22float2(hk[1]);
                float2 f2 = __half22float2(hk[2]), f3 = __half22float2(hk[3]);
                *(float4*)(kdst + u * 8)     = make_float4(f0.x, f0.y, f1.x, f1.y);
                *(float4*)(kdst + u * 8 + 4) = make_float4(f2.x, f2.y, f3.x, f3.y);
            }
        }

        // load this thread's 4 q rows (head h0+h) straight into registers
        float qv[4][20];
        #pragma unroll
        for (int qq = 0; qq < 4; ++qq) {
            const __half* qsrc = ts + (qrow_base + (size_t)qq * H_ + h0 + h) * TSH;
            uint4 v0 = *(const uint4*)qsrc;
            uint4 v1 = *(const uint4*)(qsrc + 8);
            uint2 v2 = *(const uint2*)(qsrc + 16);
            const __half2* p0 = (const __half2*)&v0;
            const __half2* p1 = (const __half2*)&v1;
            const __half2* p2 = (const __half2*)&v2;
            #pragma unroll
            for (int j = 0; j < 4; ++j) {
                float2 f = __half22float2(p0[j]);
                qv[qq][j*2] = f.x; qv[qq][j*2+1] = f.y;
            }
            #pragma unroll
            for (int j = 0; j < 4; ++j) {
                float2 f = __half22float2(p1[j]);
                qv[qq][8+j*2] = f.x; qv[qq][8+j*2+1] = f.y;
            }
            #pragma unroll
            for (int j = 0; j < 2; ++j) {
                float2 f = __half22float2(p2[j]);
                qv[qq][16+j*2] = f.x; qv[qq][16+j*2+1] = f.y;
            }
        }
        __syncthreads();   // k plane visible

        const float* kplane = ks + h * PLANE;
        const size_t obase = ((size_t)(b * L_ + q0 + qg * 4) * L_ + k0 + kg * 8) * H_
                           + h0 + h;

        #pragma unroll
        for (int kk = 0; kk < 8; ++kk) {
            size_t okk = obase + (size_t)kk * H_;
            if (maskr[kk]) {       // warp-uniform branch
                float kv[20];
                const float* kp = kplane + (kg * 8 + kk) * 24;
                #pragma unroll
                for (int u = 0; u < 5; ++u)
                    *(float4*)&kv[u * 4] = *(const float4*)(kp + u * 4);
                #pragma unroll
                for (int qq = 0; qq < 4; ++qq) {
                    float a0 = 0.f, a1 = 0.f;
                    #pragma unroll
                    for (int c = 0; c < 10; ++c) {
                        a0 = fmaf(qv[qq][2*c],   kv[2*c],   a0);
                        a1 = fmaf(qv[qq][2*c+1], kv[2*c+1], a1);
                    }
                    size_t oidx = okk + (size_t)qq * (L_ * H_);
                    out[oidx] = (a0 + a1) + bias[oidx];
                }
            } else {
                #pragma unroll
                for (int qq = 0; qq < 4; ++qq)
                    out[okk + (size_t)qq * (L_ * H_)] = 0.0f;
            }
        }
    }
}

// ---------------------------------------------------------------------------
// launch
// ---------------------------------------------------------------------------
extern "C" void kernel_launch(void* const* d_in, const int* in_sizes, int n_in,
                              void* d_out, int out_size)
{
    const float* x      = (const float*)d_in[0];   // (B,L,T)
    const int*   mask   = (const int*)  d_in[1];   // (B,L) int32
    const float* bias   = (const float*)d_in[2];   // (B,L,L,H)
    const float* W_up   = (const float*)d_in[3];   // (E,T)
    const float* W_proj = (const float*)d_in[4];   // (2E,E)
    float* out = (float*)d_out;

    __half *xh, *wuh, *wph, *xeh, *ts;
    cudaGetSymbolAddress((void**)&xh,  g_xh);
    cudaGetSymbolAddress((void**)&wuh, g_wuh);
    cudaGetSymbolAddress((void**)&wph, g_wph);
    cudaGetSymbolAddress((void**)&xeh, g_xeh);
    cudaGetSymbolAddress((void**)&ts,  g_ts);

    cudaFuncSetAttribute(gemm_f16<0>,
                         cudaFuncAttributeMaxDynamicSharedMemorySize, GSMEM_BYTES);
    cudaFuncSetAttribute(gemm_f16<2>,
                         cudaFuncAttributeMaxDynamicSharedMemorySize, GSMEM_BYTES);

    // f32 -> f16 conversions
    f2h_kernel<<<512,  256>>>((const float4*)x,      (uint2*)xh,  B_*L_*T_/4);
    f2h_kernel<<<1024, 256>>>((const float4*)W_up,   (uint2*)wuh, E_*T_/4);
    f2h_kernel<<<2048, 256>>>((const float4*)W_proj, (uint2*)wph, F_*E_/4);

    // GEMM1: xe_h(1024,2560) = x_h @ W_up_h^T
    {
        dim3 grid(B_*L_ / BM, E_ / BN);
        gemm_f16<0><<<grid, 256, GSMEM_BYTES>>>(xh, wuh, xeh, B_*L_, E_, T_);
    }
    // GEMM2: ts split layout = xe_h @ W_proj_h^T
    {
        dim3 grid(B_*L_ / BM, F_ / BN);
        gemm_f16<2><<<grid, 256, GSMEM_BYTES>>>(xeh, wph, ts, B_*L_, F_, E_);
    }
    // fused q.k^T + bias + mask epilogue
    {
        dim3 grid(L_ / 32, L_ / 32, B_);
        attn_epilogue_kernel<<<grid, 256>>>(ts, mask, bias, out);
    }
}

// round 8
// speedup vs baseline: 2.1024x; 1.0981x over previous
#include <cuda_runtime.h>
#include <cuda_fp16.h>
#include <cstdint>

#define B_  2
#define L_  512
#define T_  1024
#define E_  2560
#define H_  128
#define F_  (2*E_)   // 5120
#define TSH 48       // halves per (l,h) in ts: q[20] pad[4] k[20] pad[4]

// Scratch (no cudaMalloc allowed)
__device__ __half g_xh [B_*L_*T_];      // x fp16        2 MB
__device__ __half g_wuh[E_*T_];         // W_up fp16     5 MB
__device__ __half g_wph[F_*E_];         // W_proj fp16   26 MB
__device__ __half g_xeh[B_*L_*E_];      // xe fp16       5 MB
__device__ __half g_ts [B_*L_*H_*TSH]; // split q|k fp16 12.6 MB

// ---------------------------------------------------------------------------
// helpers
// ---------------------------------------------------------------------------
__device__ __forceinline__ uint32_t smem_u32(const void* p) {
    uint32_t a;
    asm("{ .reg .u64 t; cvta.to.shared.u64 t, %1; cvt.u32.u64 %0, t; }"
        : "=r"(a) : "l"(p));
    return a;
}

__device__ __forceinline__ void cp_async16(uint32_t smem, const void* g) {
    asm volatile("cp.async.cg.shared.global [%0], [%1], 16;" :: "r"(smem), "l"(g));
}

__device__ __forceinline__ void ldsm_x4(uint32_t (&r)[4], uint32_t addr) {
    asm volatile("ldmatrix.sync.aligned.m8n8.x4.shared.b16 {%0,%1,%2,%3}, [%4];"
                 : "=r"(r[0]), "=r"(r[1]), "=r"(r[2]), "=r"(r[3]) : "r"(addr));
}

__device__ __forceinline__ void mma_f16(float (&d)[4], const uint32_t (&a)[4],
                                        const uint32_t b0, const uint32_t b1) {
    asm volatile(
        "mma.sync.aligned.m16n8k16.row.col.f32.f16.f16.f32 "
        "{%0,%1,%2,%3}, {%4,%5,%6,%7}, {%8,%9}, {%0,%1,%2,%3};"
        : "+f"(d[0]), "+f"(d[1]), "+f"(d[2]), "+f"(d[3])
        : "r"(a[0]), "r"(a[1]), "r"(a[2]), "r"(a[3]), "r"(b0), "r"(b1));
}

// ---------------------------------------------------------------------------
// f32 -> f16 conversion (vectorized, grid-stride)
// ---------------------------------------------------------------------------
__global__ void f2h_kernel(const float4* __restrict__ in, uint2* __restrict__ out,
                           int n4)
{
    for (int i = blockIdx.x * blockDim.x + threadIdx.x; i < n4;
         i += gridDim.x * blockDim.x) {
        float4 v = in[i];
        __half2 lo = __floats2half2_rn(v.x, v.y);
        __half2 hi = __floats2half2_rn(v.z, v.w);
        uint2 o;
        o.x = *(const uint32_t*)&lo;
        o.y = *(const uint32_t*)&hi;
        out[i] = o;
    }
}

// ---------------------------------------------------------------------------
// fp16 GEMM: C[M,N] = A[M,K] * W[N,K]^T, BMT x 128 x 32 tiles, 4-stage
// cp.async. BMT=64 for fine-grained wave balance (occ 3).
// MODE 0: plain __half row-major out.
// MODE 2: split-ts out: col n -> head h=n/40, c=n%40; c<20 -> q slot (scaled
//         by 20^-0.5) at pos c, else k slot at pos c+4; row m -> ts[m][h][48].
// ---------------------------------------------------------------------------
#define BN 128
#define BK 32
#define STAGES 4
#define ROWB 80                      // 32 data halves + 8 pad = 80 B/row

template <int BMT, int MODE>
__global__ void __launch_bounds__(256, 3) gemm_f16(
    const __half* __restrict__ A, const __half* __restrict__ W,
    __half* __restrict__ C, int M, int N, int K)
{
    constexpr int M_IT = BMT / 32;          // warp m16 tiles (warp tile BMT/2)
    constexpr int A_BYTES = BMT * ROWB;
    constexpr int STGB = (BMT + BN) * ROWB;

    extern __shared__ __align__(16) char gsm[];
    const uint32_t sBase = smem_u32(gsm);

    const int tid  = threadIdx.x;
    const int warp = tid >> 5;
    const int lane = tid & 31;
    const int wm = (warp >> 2) * (BMT / 2);
    const int wn = (warp & 3) * 32;
    const int m0 = blockIdx.x * BMT;
    const int n0 = blockIdx.y * BN;

    float acc[M_IT][4][4];
    #pragma unroll
    for (int i = 0; i < M_IT; ++i)
        #pragma unroll
        for (int j = 0; j < 4; ++j)
            #pragma unroll
            for (int v = 0; v < 4; ++v) acc[i][j][v] = 0.0f;

    const int KT = K / BK;
    const int lrow = tid >> 2;          // 0..63
    const int lch  = (tid & 3) * 8;     // halves offset (16B chunks)

    #define LOAD_STAGE(st, kt)                                                  \
    {                                                                           \
        const int kb = (kt) * BK;                                               \
        const uint32_t as = sBase + (st) * STGB;                                \
        const uint32_t ws = as + A_BYTES;                                       \
        _Pragma("unroll")                                                       \
        for (int i = 0; i < BMT / 64; ++i) {                                    \
            int row = lrow + i * 64;                                            \
            cp_async16(as + row * ROWB + lch * 2,                               \
                       &A[(size_t)(m0 + row) * K + kb + lch]);                  \
        }                                                                       \
        _Pragma("unroll")                                                       \
        for (int i = 0; i < 2; ++i) {                                           \
            int row = lrow + i * 64;                                            \
            cp_async16(ws + row * ROWB + lch * 2,                               \
                       &W[(size_t)(n0 + row) * K + kb + lch]);                  \
        }                                                                       \
        asm volatile("cp.async.commit_group;");                                 \
    }

    LOAD_STAGE(0, 0);
    LOAD_STAGE(1, 1);
    LOAD_STAGE(2, 2);

    const int sel  = lane >> 3;
    const int lr8  = lane & 7;
    const int selR = (sel & 1) * 8;
    const int selK = (sel >> 1) * 16;

    for (int kt = 0; kt < KT; ++kt) {
        asm volatile("cp.async.wait_group 2;");
        __syncthreads();

        const int st = kt & 3;
        const uint32_t as = sBase + st * STGB;
        const uint32_t ws = as + A_BYTES;

        #pragma unroll
        for (int s = 0; s < 2; ++s) {
            const int kbyte = s * 32 + selK;
            uint32_t af[M_IT][4];
            #pragma unroll
            for (int i = 0; i < M_IT; ++i) {
                int m = wm + i * 16 + selR + lr8;
                ldsm_x4(af[i], as + m * ROWB + kbyte);
            }
            uint32_t bf[4][2];
            #pragma unroll
            for (int j2 = 0; j2 < 2; ++j2) {
                uint32_t r[4];
                int n = wn + j2 * 16 + selR + lr8;
                ldsm_x4(r, ws + n * ROWB + kbyte);
                bf[j2*2][0]   = r[0]; bf[j2*2][1]   = r[2];
                bf[j2*2+1][0] = r[1]; bf[j2*2+1][1] = r[3];
            }
            #pragma unroll
            for (int i = 0; i < M_IT; ++i)
                #pragma unroll
                for (int j = 0; j < 4; ++j)
                    mma_f16(acc[i][j], af[i], bf[j][0], bf[j][1]);
        }
        __syncthreads();

        if (kt + 3 < KT) {
            LOAD_STAGE((kt + 3) & 3, kt + 3);
        } else {
            asm volatile("cp.async.commit_group;");
        }
    }

    const int er = lane >> 2;
    const int ec = (lane & 3) * 2;
    #pragma unroll
    for (int i = 0; i < M_IT; ++i) {
        #pragma unroll
        for (int j = 0; j < 4; ++j) {
            int m = m0 + wm + i * 16 + er;
            int n = n0 + wn + j * 8 + ec;
            if (MODE == 0) {
                __half2 h0 = __floats2half2_rn(acc[i][j][0], acc[i][j][1]);
                __half2 h1 = __floats2half2_rn(acc[i][j][2], acc[i][j][3]);
                *(__half2*)(C + (size_t)m * N + n)       = h0;
                *(__half2*)(C + (size_t)(m + 8) * N + n) = h1;
            } else {
                int h  = n / 40;
                int cc = n % 40;
                bool isq = cc < 20;
                int pos = isq ? cc : cc + 4;
                float s = isq ? 0.22360679774997896f : 1.0f;
                __half2 h0 = __floats2half2_rn(acc[i][j][0] * s, acc[i][j][1] * s);
                __half2 h1 = __floats2half2_rn(acc[i][j][2] * s, acc[i][j][3] * s);
                *(__half2*)(C + ((size_t)m * H_ + h) * TSH + pos)       = h0;
                *(__half2*)(C + ((size_t)(m + 8) * H_ + h) * TSH + pos) = h1;
            }
        }
    }
    #undef LOAD_STAGE
}

#define GSMEM_BYTES ((64 + BN) * ROWB * STAGES)   // 61440

// ---------------------------------------------------------------------------
// Epilogue v5: block = (head-chunk 8h, q-tile 32, b). q regs loaded ONCE;
// k streamed through smem over 16 k-iterations of 32 rows.
// Thread: h = tid&7, qg = (tid>>3)&7 (4 q rows), kg = tid>>6 (8 k rows/iter).
// k smem: 8 planes x 772 f32 (stride 772 === 4 mod 32 -> conflict-free).
// mask warp-uniform per kk -> skip k load + FMA + bias read when 0.
// ---------------------------------------------------------------------------
#define PLANE 772
#define EPK_WORDS (8*PLANE)   // 24704 B

__global__ void __launch_bounds__(256, 2) attn_epilogue_kernel(
    const __half* __restrict__ ts, const int* __restrict__ mask,
    const float* __restrict__ bias, float* __restrict__ out)
{
    __shared__ __align__(16) float ks[EPK_WORDS];

    const int b  = blockIdx.z;
    const int q0 = blockIdx.y * 32;
    const int h0 = blockIdx.x * 8;
    const int tid = threadIdx.x;
    const int h  = tid & 7;
    const int qg = (tid >> 3) & 7;   // 4 q rows each
    const int kg = tid >> 6;         // 8 k rows per iter (warp-uniform)
    const int frow = tid >> 3;       // fill: 0..31
    const int fh   = tid & 7;        // fill: 0..7

    // ---- load this thread's 4 q rows (head h0+h) into registers, once ----
    float qv[4][20];
    {
        const size_t qrow_base = (size_t)(b * L_ + q0 + qg * 4) * H_;
        #pragma unroll
        for (int qq = 0; qq < 4; ++qq) {
            const __half* qsrc = ts + (qrow_base + (size_t)qq * H_ + h0 + h) * TSH;
            uint4 v0 = *(const uint4*)qsrc;
            uint4 v1 = *(const uint4*)(qsrc + 8);
            uint2 v2 = *(const uint2*)(qsrc + 16);
            const __half2* p0 = (const __half2*)&v0;
            const __half2* p1 = (const __half2*)&v1;
            const __half2* p2 = (const __half2*)&v2;
            #pragma unroll
            for (int j = 0; j < 4; ++j) {
                float2 f = __half22float2(p0[j]);
                qv[qq][j*2] = f.x; qv[qq][j*2+1] = f.y;
            }
            #pragma unroll
            for (int j = 0; j < 4; ++j) {
                float2 f = __half22float2(p1[j]);
                qv[qq][8+j*2] = f.x; qv[qq][8+j*2+1] = f.y;
            }
            #pragma unroll
            for (int j = 0; j < 2; ++j) {
                float2 f = __half22float2(p2[j]);
                qv[qq][16+j*2] = f.x; qv[qq][16+j*2+1] = f.y;
            }
        }
    }

    for (int kt = 0; kt < 16; ++kt) {
        const int k0 = kt * 32;
        __syncthreads();   // previous iteration's consumers done with ks

        // fill k plane: one (row, head) segment per thread, 20 halves -> f32
        {
            const __half* ksrc = ts + ((size_t)(b * L_ + k0 + frow) * H_ + h0 + fh) * TSH + 24;
            float* kdst = ks + fh * PLANE + frow * 24;
            #pragma unroll
            for (int u = 0; u < 3; ++u) {
                uint4 vk = *(const uint4*)(ksrc + u * 8);
                const __half2* hk = (const __half2*)&vk;
                float2 f0 = __half22float2(hk[0]), f1 = __half22float2(hk[1]);
                float2 f2 = __half22float2(hk[2]), f3 = __half22float2(hk[3]);
                *(float4*)(kdst + u * 8)     = make_float4(f0.x, f0.y, f1.x, f1.y);
                *(float4*)(kdst + u * 8 + 4) = make_float4(f2.x, f2.y, f3.x, f3.y);
            }
        }
        __syncthreads();   // k plane visible

        int maskr[8];
        #pragma unroll
        for (int kk = 0; kk < 8; ++kk)
            maskr[kk] = mask[b * L_ + k0 + kg * 8 + kk];

        const float* kplane = ks + h * PLANE;
        const size_t obase = ((size_t)(b * L_ + q0 + qg * 4) * L_ + k0 + kg * 8) * H_
                           + h0 + h;

        #pragma unroll
        for (int kk = 0; kk < 8; ++kk) {
            size_t okk = obase + (size_t)kk * H_;
            if (maskr[kk]) {       // warp-uniform branch
                float kv[20];
                const float* kp = kplane + (kg * 8 + kk) * 24;
                #pragma unroll
                for (int u = 0; u < 5; ++u)
                    *(float4*)&kv[u * 4] = *(const float4*)(kp + u * 4);
                #pragma unroll
                for (int qq = 0; qq < 4; ++qq) {
                    float a0 = 0.f, a1 = 0.f;
                    #pragma unroll
                    for (int c = 0; c < 10; ++c) {
                        a0 = fmaf(qv[qq][2*c],   kv[2*c],   a0);
                        a1 = fmaf(qv[qq][2*c+1], kv[2*c+1], a1);
                    }
                    size_t oidx = okk + (size_t)qq * (L_ * H_);
                    out[oidx] = (a0 + a1) + bias[oidx];
                }
            } else {
                #pragma unroll
                for (int qq = 0; qq < 4; ++qq)
                    out[okk + (size_t)qq * (L_ * H_)] = 0.0f;
            }
        }
    }
}

// ---------------------------------------------------------------------------
// launch
// ---------------------------------------------------------------------------
extern "C" void kernel_launch(void* const* d_in, const int* in_sizes, int n_in,
                              void* d_out, int out_size)
{
    const float* x      = (const float*)d_in[0];   // (B,L,T)
    const int*   mask   = (const int*)  d_in[1];   // (B,L) int32
    const float* bias   = (const float*)d_in[2];   // (B,L,L,H)
    const float* W_up   = (const float*)d_in[3];   // (E,T)
    const float* W_proj = (const float*)d_in[4];   // (2E,E)
    float* out = (float*)d_out;

    __half *xh, *wuh, *wph, *xeh, *ts;
    cudaGetSymbolAddress((void**)&xh,  g_xh);
    cudaGetSymbolAddress((void**)&wuh, g_wuh);
    cudaGetSymbolAddress((void**)&wph, g_wph);
    cudaGetSymbolAddress((void**)&xeh, g_xeh);
    cudaGetSymbolAddress((void**)&ts,  g_ts);

    cudaFuncSetAttribute((const void*)gemm_f16<64, 0>,
                         cudaFuncAttributeMaxDynamicSharedMemorySize, GSMEM_BYTES);
    cudaFuncSetAttribute((const void*)gemm_f16<64, 2>,
                         cudaFuncAttributeMaxDynamicSharedMemorySize, GSMEM_BYTES);

    // f32 -> f16 conversions
    f2h_kernel<<<512,  256>>>((const float4*)x,      (uint2*)xh,  B_*L_*T_/4);
    f2h_kernel<<<1024, 256>>>((const float4*)W_up,   (uint2*)wuh, E_*T_/4);
    f2h_kernel<<<2048, 256>>>((const float4*)W_proj, (uint2*)wph, F_*E_/4);

    // GEMM1: xe_h(1024,2560) = x_h @ W_up_h^T
    {
        dim3 grid(B_*L_ / 64, E_ / BN);
        gemm_f16<64, 0><<<grid, 256, GSMEM_BYTES>>>(xh, wuh, xeh, B_*L_, E_, T_);
    }
    // GEMM2: ts split layout = xe_h @ W_proj_h^T
    {
        dim3 grid(B_*L_ / 64, F_ / BN);
        gemm_f16<64, 2><<<grid, 256, GSMEM_BYTES>>>(xeh, wph, ts, B_*L_, F_, E_);
    }
    // fused q.k^T + bias + mask epilogue
    {
        dim3 grid(H_ / 8, L_ / 32, B_);
        attn_epilogue_kernel<<<grid, 256>>>(ts, mask, bias, out);
    }
}